// round 17
// baseline (speedup 1.0000x reference)
#include <cuda_runtime.h>
#include <cuda_bf16.h>
#include <cuda_fp16.h>
#include <cstdint>

#define Bv      2
#define Sv      4096
#define QKVD    2048
#define NHEAD   16
#define NKVH    8
#define HDIM    64
#define NFEAT   64
#define CHUNK   128
#define NCHUNK  32
#define MROWS   (Bv*Sv)

// ---------------- scratch (device globals; no allocs allowed) ----------------
__device__ __half g_qkvh[(size_t)MROWS*QKVD];    // qkv fp16
__device__ float g_qp  [(size_t)MROWS*NHEAD*NFEAT];
__device__ float g_kp  [(size_t)MROWS*NKVH*NFEAT];
__device__ float g_z   [(size_t)Bv*NKVH*Sv];
__device__ float g_kvc [(size_t)Bv*NKVH*NCHUNK*NFEAT*HDIM];

__device__ __half g_ah [(size_t)MROWS*1024];     // attn activations fp16
__device__ __half g_w1 [(size_t)2048*1024];      // W_qkv fp16
__device__ __half g_w2 [(size_t)1024*1024];      // W_o fp16

// ---------------- PTX helpers -------------------------------------------------
__device__ __forceinline__ uint32_t smem_u32(const void* p) {
    uint32_t a;
    asm("{ .reg .u64 t; cvta.to.shared.u64 t, %1; cvt.u32.u64 %0, t; }" : "=r"(a) : "l"(p));
    return a;
}
__device__ __forceinline__ void ldsm_x4(uint32_t& r0, uint32_t& r1,
                                        uint32_t& r2, uint32_t& r3, uint32_t a) {
    asm volatile("ldmatrix.sync.aligned.m8n8.x4.shared.b16 {%0,%1,%2,%3}, [%4];"
                 : "=r"(r0), "=r"(r1), "=r"(r2), "=r"(r3) : "r"(a));
}
__device__ __forceinline__ void ldsm_x2(uint32_t& r0, uint32_t& r1, uint32_t a) {
    asm volatile("ldmatrix.sync.aligned.m8n8.x2.shared.b16 {%0,%1}, [%2];"
                 : "=r"(r0), "=r"(r1) : "r"(a));
}
__device__ __forceinline__ void ldsm_x2_t(uint32_t& r0, uint32_t& r1, uint32_t a) {
    asm volatile("ldmatrix.sync.aligned.m8n8.x2.trans.shared.b16 {%0,%1}, [%2];"
                 : "=r"(r0), "=r"(r1) : "r"(a));
}
__device__ __forceinline__ void mma_f16_f32(float* d,
    uint32_t a0, uint32_t a1, uint32_t a2, uint32_t a3, uint32_t b0, uint32_t b1) {
    asm volatile(
        "mma.sync.aligned.m16n8k16.row.col.f32.f16.f16.f32 "
        "{%0,%1,%2,%3}, {%4,%5,%6,%7}, {%8,%9}, {%0,%1,%2,%3};"
        : "+f"(d[0]), "+f"(d[1]), "+f"(d[2]), "+f"(d[3])
        : "r"(a0), "r"(a1), "r"(a2), "r"(a3), "r"(b0), "r"(b1));
}
__device__ __forceinline__ uint32_t pack2h(float x, float y) {
    __half hx = __float2half(x), hy = __float2half(y);
    return (uint32_t)__half_as_ushort(hx) |
           ((uint32_t)__half_as_ushort(hy) << 16);
}

// ---------------- fp32 -> fp16 convert (weights) -------------------------------
__global__ void __launch_bounds__(256) cvt_h_kernel(
    const float* __restrict__ src, __half* __restrict__ dst, int n)
{
    int i = (blockIdx.x * 256 + threadIdx.x) * 4;
    if (i >= n) return;
    float4 v = *(const float4*)(src + i);
    __half2* dp = (__half2*)(dst + i);
    dp[0] = __half2(__float2half(v.x), __float2half(v.y));
    dp[1] = __half2(__float2half(v.z), __float2half(v.w));
}

// ---------------- mma.sync GEMM (1-pass fp16): C = A[M,K] * B[N,K]^T ----------
// Templated: A may be fp32 (converted during SMEM fill), C may be fp16.
#define GM_PAD  40
#define GM_BUF  (128*GM_PAD)
#define GM_SMEM (2*2*GM_BUF*2)

__device__ __forceinline__ void gm_load_a(uint4* dst, const __half* p) {
    dst[0] = *(const uint4*)p;
    dst[1] = *(const uint4*)(p + 8);
}
__device__ __forceinline__ void gm_load_a(uint4* dst, const float* p) {
    float4 f0 = *(const float4*)p;
    float4 f1 = *(const float4*)(p + 4);
    float4 f2 = *(const float4*)(p + 8);
    float4 f3 = *(const float4*)(p + 12);
    uint4 u0, u1;
    u0.x = pack2h(f0.x, f0.y); u0.y = pack2h(f0.z, f0.w);
    u0.z = pack2h(f1.x, f1.y); u0.w = pack2h(f1.z, f1.w);
    u1.x = pack2h(f2.x, f2.y); u1.y = pack2h(f2.z, f2.w);
    u1.z = pack2h(f3.x, f3.y); u1.w = pack2h(f3.z, f3.w);
    dst[0] = u0; dst[1] = u1;
}
__device__ __forceinline__ void gm_store_c(float* C, size_t idx, float a, float b) {
    float2 v = {a, b};
    *(float2*)&C[idx] = v;
}
__device__ __forceinline__ void gm_store_c(__half* C, size_t idx, float a, float b) {
    *(uint32_t*)&C[idx] = pack2h(a, b);
}

template<typename TA, typename TC>
__global__ void __launch_bounds__(256) gemm_mma_kernel(
    const TA* __restrict__ A, const __half* __restrict__ B,
    TC* __restrict__ C, int N, int K)
{
    extern __shared__ __half smh[];
    const int tid = threadIdx.x;
    const int m0 = blockIdx.y * 128, n0 = blockIdx.x * 128;
    const int row = tid >> 1, off = (tid & 1) * 16;

    const TA*     gp0 = A + (size_t)(m0 + row) * K + off;
    const __half* gp1 = B + (size_t)(n0 + row) * K + off;

    const int wid = tid >> 5, lane = tid & 31;
    const int wm = wid >> 2, wn = wid & 3;
    const int l16 = lane & 15;

    float acc[4][4][4];
    #pragma unroll
    for (int mi = 0; mi < 4; mi++)
        #pragma unroll
        for (int ni = 0; ni < 4; ni++)
            #pragma unroll
            for (int r = 0; r < 4; r++) acc[mi][ni][r] = 0.f;

    const int sto = row * GM_PAD + off;
    uint4 ldA[2], ldB[2];

    gm_load_a(ldA, gp0);
    ldB[0] = *(const uint4*)gp1; ldB[1] = *(const uint4*)(gp1 + 8);
    *(uint4*)&smh[sto]              = ldA[0];
    *(uint4*)&smh[sto + 8]          = ldA[1];
    *(uint4*)&smh[GM_BUF + sto]     = ldB[0];
    *(uint4*)&smh[GM_BUF + sto + 8] = ldB[1];
    __syncthreads();

    const int NKT = K >> 5;
    for (int kt = 0; kt < NKT; kt++) {
        const int b = kt & 1;
        if (kt + 1 < NKT) {
            const int kb = (kt + 1) << 5;
            gm_load_a(ldA, gp0 + kb);
            ldB[0] = *(const uint4*)(gp1 + kb); ldB[1] = *(const uint4*)(gp1 + kb + 8);
        }

        const __half* sA = smh + b*(2*GM_BUF);
        const __half* sB = sA + GM_BUF;

        #pragma unroll
        for (int k16 = 0; k16 < 32; k16 += 16) {
            uint32_t af[4][4];
            #pragma unroll
            for (int mi = 0; mi < 4; mi++) {
                int roff = (wm*64 + mi*16 + l16) * GM_PAD + k16 + (lane >> 4) * 8;
                ldsm_x4(af[mi][0], af[mi][1], af[mi][2], af[mi][3], smem_u32(sA + roff));
            }
            #pragma unroll
            for (int ni = 0; ni < 4; ni++) {
                int boff = (wn*32 + ni*8 + (l16 & 7)) * GM_PAD + k16 + ((l16 >> 3) & 1) * 8;
                uint32_t b0, b1;
                ldsm_x2(b0, b1, smem_u32(sB + boff));
                #pragma unroll
                for (int mi = 0; mi < 4; mi++)
                    mma_f16_f32(acc[mi][ni], af[mi][0], af[mi][1], af[mi][2], af[mi][3], b0, b1);
            }
        }

        if (kt + 1 < NKT) {
            __half* dst = smh + (b ^ 1)*(2*GM_BUF);
            *(uint4*)&dst[sto]              = ldA[0];
            *(uint4*)&dst[sto + 8]          = ldA[1];
            *(uint4*)&dst[GM_BUF + sto]     = ldB[0];
            *(uint4*)&dst[GM_BUF + sto + 8] = ldB[1];
        }
        __syncthreads();
    }

    const int g = lane >> 2, tg = lane & 3;
    #pragma unroll
    for (int mi = 0; mi < 4; mi++) {
        #pragma unroll
        for (int ni = 0; ni < 4; ni++) {
            int r0 = m0 + wm*64 + mi*16 + g;
            int c0 = n0 + wn*32 + ni*8 + tg*2;
            gm_store_c(C, (size_t)r0 * N + c0,       acc[mi][ni][0], acc[mi][ni][1]);
            gm_store_c(C, (size_t)(r0 + 8) * N + c0, acc[mi][ni][2], acc[mi][ni][3]);
        }
    }
}

// ---------------- RoPE + relu feature projection on tensor cores -------------
#define RP_P 72
__global__ void __launch_bounds__(128) ropeproj_kernel(
    const float* __restrict__ cosg, const float* __restrict__ sing,
    const float* __restrict__ proj)
{
    __shared__ __half dat[64*RP_P];
    __shared__ __half pj [64*RP_P];
    const int tid = threadIdx.x;
    const int rbase = blockIdx.x * 64;

    #pragma unroll
    for (int j = 0; j < 32; j++) {
        int i = tid + j*128;
        int f = i >> 6, d = i & 63;
        pj[f*RP_P + d] = __float2half(proj[i]);
    }
    #pragma unroll
    for (int j = 0; j < 16; j++) {
        int e = tid + j*128;
        int r = e >> 5, d = e & 31;
        int rho = rbase + r;
        int bs  = rho / 24;
        int h   = rho - bs*24;
        int s   = bs & (Sv-1);
        size_t base = (size_t)bs*QKVD + h*64;
        float x1 = __half2float(g_qkvh[base + d]);
        float x2 = __half2float(g_qkvh[base + d + 32]);
        float cc = cosg[s*64 + d];
        float ss = sing[s*64 + d];
        dat[r*RP_P + d]      = __float2half(fmaf(x1, cc, -x2 * ss));
        dat[r*RP_P + d + 32] = __float2half(fmaf(x2, cc,  x1 * ss));
    }
    __syncthreads();

    const int wid = tid >> 5, lane = tid & 31;
    const int l16 = lane & 15, g = lane >> 2, tg = lane & 3;
    const int mrow = wid * 16;
    const int ahalf = (lane >> 4) * 8;

    float acc[8][4];
    #pragma unroll
    for (int nt = 0; nt < 8; nt++)
        #pragma unroll
        for (int r = 0; r < 4; r++) acc[nt][r] = 0.f;

    #pragma unroll
    for (int k16 = 0; k16 < 64; k16 += 16) {
        int ro = (mrow + l16)*RP_P + k16 + ahalf;
        uint32_t a0,a1,a2,a3;
        ldsm_x4(a0,a1,a2,a3, smem_u32(dat + ro));
        #pragma unroll
        for (int nt = 0; nt < 8; nt++) {
            int bo = (nt*8 + (l16 & 7))*RP_P + k16 + ((l16 >> 3) & 1)*8;
            uint32_t b0,b1;
            ldsm_x2(b0,b1, smem_u32(pj + bo));
            mma_f16_f32(acc[nt], a0,a1,a2,a3, b0,b1);
        }
    }

    const float ratio = (float)(0.125 * (0.125 + 1e-4));
    float o[8][4];
    float rs0 = 0.f, rs1 = 0.f;
    #pragma unroll
    for (int nt = 0; nt < 8; nt++) {
        o[nt][0] = fmaxf(acc[nt][0]*ratio, 0.f);
        o[nt][1] = fmaxf(acc[nt][1]*ratio, 0.f);
        o[nt][2] = fmaxf(acc[nt][2]*ratio, 0.f);
        o[nt][3] = fmaxf(acc[nt][3]*ratio, 0.f);
        rs0 += o[nt][0] + o[nt][1];
        rs1 += o[nt][2] + o[nt][3];
    }
    rs0 += __shfl_xor_sync(0xffffffffu, rs0, 1);
    rs0 += __shfl_xor_sync(0xffffffffu, rs0, 2);
    rs1 += __shfl_xor_sync(0xffffffffu, rs1, 1);
    rs1 += __shfl_xor_sync(0xffffffffu, rs1, 2);

    #pragma unroll
    for (int half = 0; half < 2; half++) {
        int r   = mrow + g + half*8;
        int rho = rbase + r;
        int bs  = rho / 24;
        int h   = rho - bs*24;
        float rs = half ? rs1 : rs0;
        if (h < NHEAD) {
            float* dst = &g_qp[((size_t)bs*NHEAD + h)*NFEAT];
            #pragma unroll
            for (int nt = 0; nt < 8; nt++) {
                float2 v = {o[nt][half*2] + 1e-4f, o[nt][half*2+1] + 1e-4f};
                *(float2*)&dst[nt*8 + tg*2] = v;
            }
        } else {
            int kvh = h - NHEAD;
            int b = bs >> 12, t = bs & 4095;
            float* dst = &g_kp[((size_t)bs*NKVH + kvh)*NFEAT];
            #pragma unroll
            for (int nt = 0; nt < 8; nt++) {
                float2 v = {o[nt][half*2], o[nt][half*2+1]};
                *(float2*)&dst[nt*8 + tg*2] = v;
            }
            if (tg == 0) g_z[((size_t)(b*NKVH + kvh))*Sv + t] = rs;
        }
    }
}

// ---------------- inclusive scan of g_z per (b,kvh), in place -----------------
__global__ void __launch_bounds__(256) zscan_kernel()
{
    const int bkv = blockIdx.x;
    const int tid = threadIdx.x;
    const int lane = tid & 31, warp = tid >> 5;
    __shared__ float wsum[8];
    float carry = 0.f;

    for (int tile = 0; tile < 16; tile++) {
        int t = tile*256 + tid;
        float x = g_z[(size_t)bkv*Sv + t];
        #pragma unroll
        for (int o = 1; o < 32; o <<= 1) {
            float n = __shfl_up_sync(0xffffffffu, x, o);
            if (lane >= o) x += n;
        }
        if (lane == 31) wsum[warp] = x;
        __syncthreads();
        float off = carry;
        for (int w2 = 0; w2 < warp; w2++) off += wsum[w2];
        g_z[(size_t)bkv*Sv + t] = off + x;
        float tot = 0.f;
        #pragma unroll
        for (int w2 = 0; w2 < 8; w2++) tot += wsum[w2];
        carry += tot;
        __syncthreads();
    }
}

// ---------------- per-chunk KV = Kp^T V (64x64) via mma.sync ------------------
#define CK_KT 136
#define CK_VP 72
__global__ void __launch_bounds__(128) chunkkv_kernel()
{
    __shared__ __half Kt[64*CK_KT];   // [f][t]
    __shared__ __half Vs[128*CK_VP];  // [t][d]
    const int c   = blockIdx.x;
    const int bkv = blockIdx.y;
    const int b   = bkv >> 3, kvh = bkv & 7;
    const int tid = threadIdx.x;

    #pragma unroll
    for (int j = 0; j < 64; j++) {
        int e = tid + j*128;
        int t = e >> 6, f = e & 63;
        size_t bs = (size_t)(b*Sv + c*CHUNK + t);
        Kt[f*CK_KT + t] = __float2half(g_kp[(bs*NKVH + kvh)*NFEAT + f]);
        Vs[t*CK_VP + f] = g_qkvh[bs*QKVD + 1536 + kvh*64 + f];
    }
    __syncthreads();

    const int wid = tid >> 5, lane = tid & 31;
    const int l16 = lane & 15, g = lane >> 2, tg = lane & 3;
    const int mrow = wid * 16;
    const int ahalf = (lane >> 4) * 8;

    float acc[8][4];
    #pragma unroll
    for (int nt = 0; nt < 8; nt++)
        #pragma unroll
        for (int r = 0; r < 4; r++) acc[nt][r] = 0.f;

    #pragma unroll
    for (int k16 = 0; k16 < 128; k16 += 16) {
        int ro = (mrow + l16)*CK_KT + k16 + ahalf;
        uint32_t a0,a1,a2,a3;
        ldsm_x4(a0,a1,a2,a3, smem_u32(Kt + ro));
        #pragma unroll
        for (int nt = 0; nt < 8; nt++) {
            int bo = (k16 + l16)*CK_VP + nt*8;
            uint32_t b0,b1;
            ldsm_x2_t(b0,b1, smem_u32(Vs + bo));
            mma_f16_f32(acc[nt], a0,a1,a2,a3, b0,b1);
        }
    }

    size_t base = ((size_t)bkv*NCHUNK + c)*4096;
    #pragma unroll
    for (int nt = 0; nt < 8; nt++) {
        int r0 = mrow + g, r1 = r0 + 8;
        int c0 = nt*8 + tg*2;
        float2 v0 = {acc[nt][0], acc[nt][1]};
        float2 v1 = {acc[nt][2], acc[nt][3]};
        *(float2*)&g_kvc[base + (size_t)r0*64 + c0] = v0;
        *(float2*)&g_kvc[base + (size_t)r1*64 + c0] = v1;
    }
}

// ---------------- exclusive chunk-prefix of KV, in place (16x4 blocks) --------
__global__ void __launch_bounds__(256) kvprefix_kernel()
{
    const int bkv = blockIdx.x;
    const int seg = blockIdx.y;        // quarter of the 4096-float vector
    const int tid = threadIdx.x;
    const int e0  = seg*1024 + tid;
    float acc[4];
    #pragma unroll
    for (int j = 0; j < 4; j++) acc[j] = 0.f;
    for (int c = 0; c < NCHUNK; c++) {
        size_t base = ((size_t)bkv*NCHUNK + c)*4096 + e0;
        #pragma unroll
        for (int j = 0; j < 4; j++) {
            size_t idx = base + j*256;
            float cur = g_kvc[idx];
            g_kvc[idx] = acc[j];
            acc[j] += cur;
        }
    }
}

// ---------------- stage D: 1-pass fp16 causal combine ------------------------
#define SD_QP  72
#define SD_SP  136
#define O_Q    0
#define O_K    9216
#define O_V    18432
#define O_C    27648
#define O_S    32256
#define SD_HALVES 49664
#define SD_BYTES  (SD_HALVES*2 + 512)

__global__ void __launch_bounds__(256) stage_d_kernel()
{
    extern __shared__ __half shd[];
    __half* sQ = shd + O_Q;
    __half* sK = shd + O_K;
    __half* sV = shd + O_V;
    __half* sC = shd + O_C;
    __half* sS = shd + O_S;
    float* dinv = (float*)(shd + SD_HALVES);

    const int c   = blockIdx.x;
    const int h   = blockIdx.y;
    const int b   = blockIdx.z;
    const int kvh = h >> 1;
    const int tid = threadIdx.x;
    const size_t t0 = (size_t)b*Sv + c*CHUNK;

    #pragma unroll
    for (int j = 0; j < 32; j++) {
        int e = tid + j*256;
        int t = e >> 6, f = e & 63;
        sQ[t*SD_QP + f] = __float2half(g_qp[((t0 + t)*NHEAD + h)*NFEAT + f]);
        sK[t*SD_QP + f] = __float2half(g_kp[((t0 + t)*NKVH + kvh)*NFEAT + f]);
        sV[t*SD_QP + f] = g_qkvh[(t0 + t)*QKVD + 1536 + kvh*64 + f];
    }
    #pragma unroll
    for (int j = 0; j < 16; j++) {
        int e = tid + j*256;
        int f = e >> 6, d = e & 63;
        sC[f*SD_QP + d] = __float2half(
            g_kvc[(((size_t)(b*NKVH + kvh))*NCHUNK + c)*4096 + e]);
    }
    __syncthreads();

    if (tid < 128) {
        float s = 0.f;
        #pragma unroll
        for (int f = 0; f < 64; f++)
            s += __half2float(sQ[tid*SD_QP + f]);
        float z = g_z[((size_t)(b*NKVH + kvh))*Sv + c*CHUNK + tid];
        dinv[tid] = 1.0f / (s*z + 1e-6f);
    }
    __syncthreads();

    const int wid = tid >> 5, lane = tid & 31;
    const int l16 = lane & 15, g = lane >> 2, tg = lane & 3;
    const int mrow = wid * 16;
    const int ahalf = (lane >> 4) * 8;

    {
        float accS[16][4];
        #pragma unroll
        for (int nt = 0; nt < 16; nt++)
            #pragma unroll
            for (int r = 0; r < 4; r++) accS[nt][r] = 0.f;

        #pragma unroll
        for (int k16 = 0; k16 < 64; k16 += 16) {
            int ro = (mrow + l16)*SD_QP + k16 + ahalf;
            uint32_t a0,a1,a2,a3;
            ldsm_x4(a0,a1,a2,a3, smem_u32(sQ + ro));
            #pragma unroll
            for (int nt = 0; nt < 16; nt++) {
                int bo = (nt*8 + (l16 & 7))*SD_QP + k16 + ((l16 >> 3) & 1)*8;
                uint32_t b0,b1;
                ldsm_x2(b0,b1, smem_u32(sK + bo));
                mma_f16_f32(accS[nt], a0,a1,a2,a3, b0,b1);
            }
        }
        #pragma unroll
        for (int nt = 0; nt < 16; nt++) {
            int r0 = mrow + g, r1 = r0 + 8;
            int c0 = nt*8 + tg*2;
            float v00 = (c0     <= r0) ? accS[nt][0] : 0.f;
            float v01 = (c0 + 1 <= r0) ? accS[nt][1] : 0.f;
            float v10 = (c0     <= r1) ? accS[nt][2] : 0.f;
            float v11 = (c0 + 1 <= r1) ? accS[nt][3] : 0.f;
            *(uint32_t*)&sS[r0*SD_SP + c0] = pack2h(v00, v01);
            *(uint32_t*)&sS[r1*SD_SP + c0] = pack2h(v10, v11);
        }
    }
    __syncwarp();

    {
        float acc[8][4];
        #pragma unroll
        for (int nt = 0; nt < 8; nt++)
            #pragma unroll
            for (int r = 0; r < 4; r++) acc[nt][r] = 0.f;

        #pragma unroll
        for (int k16 = 0; k16 < 128; k16 += 16) {
            int ro = (mrow + l16)*SD_SP + k16 + ahalf;
            uint32_t a0,a1,a2,a3;
            ldsm_x4(a0,a1,a2,a3, smem_u32(sS + ro));
            #pragma unroll
            for (int nt = 0; nt < 8; nt++) {
                int bo = (k16 + l16)*SD_QP + nt*8;
                uint32_t b0,b1;
                ldsm_x2_t(b0,b1, smem_u32(sV + bo));
                mma_f16_f32(acc[nt], a0,a1,a2,a3, b0,b1);
            }
        }
        #pragma unroll
        for (int k16 = 0; k16 < 64; k16 += 16) {
            int ro = (mrow + l16)*SD_QP + k16 + ahalf;
            uint32_t a0,a1,a2,a3;
            ldsm_x4(a0,a1,a2,a3, smem_u32(sQ + ro));
            #pragma unroll
            for (int nt = 0; nt < 8; nt++) {
                int bo = (k16 + l16)*SD_QP + nt*8;
                uint32_t b0,b1;
                ldsm_x2_t(b0,b1, smem_u32(sC + bo));
                mma_f16_f32(acc[nt], a0,a1,a2,a3, b0,b1);
            }
        }

        const int r0 = mrow + g, r1 = r0 + 8;
        const float d0 = dinv[r0], d1 = dinv[r1];
        #pragma unroll
        for (int nt = 0; nt < 8; nt++) {
            int c0 = nt*8 + tg*2;
            float o00 = acc[nt][0]*d0, o01 = acc[nt][1]*d0;
            float o10 = acc[nt][2]*d1, o11 = acc[nt][3]*d1;
            size_t a0 = (t0 + r0)*1024 + h*64 + c0;
            size_t a1 = (t0 + r1)*1024 + h*64 + c0;
            *(uint32_t*)&g_ah[a0] = pack2h(o00, o01);
            *(uint32_t*)&g_ah[a1] = pack2h(o10, o11);
        }
    }
}

// ---------------- launch ------------------------------------------------------
extern "C" void kernel_launch(void* const* d_in, const int* in_sizes, int n_in,
                              void* d_out, int out_size)
{
    const float* hidden = (const float*)d_in[0];
    const float* cosg   = (const float*)d_in[1];
    const float* sing   = (const float*)d_in[2];
    const float* W_qkv  = (const float*)d_in[3];
    const float* W_o    = (const float*)d_in[4];
    const float* proj   = (const float*)d_in[5];
    float* out = (float*)d_out;

    static bool attr_done = false;
    if (!attr_done) {
        cudaFuncSetAttribute(stage_d_kernel,
            cudaFuncAttributeMaxDynamicSharedMemorySize, SD_BYTES);
        cudaFuncSetAttribute(gemm_mma_kernel<float, __half>,
            cudaFuncAttributeMaxDynamicSharedMemorySize, GM_SMEM);
        cudaFuncSetAttribute(gemm_mma_kernel<__half, float>,
            cudaFuncAttributeMaxDynamicSharedMemorySize, GM_SMEM);
        attr_done = true;
    }

    __half *qkvh, *ah, *w1, *w2;
    cudaGetSymbolAddress((void**)&qkvh, g_qkvh);
    cudaGetSymbolAddress((void**)&ah, g_ah);
    cudaGetSymbolAddress((void**)&w1, g_w1);
    cudaGetSymbolAddress((void**)&w2, g_w2);

    // 1. convert W_qkv; QKV GEMM reads fp32 hidden directly, writes fp16 qkv
    cvt_h_kernel<<<(2048*1024)/1024, 256>>>(W_qkv, w1, 2048*1024);
    gemm_mma_kernel<float, __half><<<dim3(QKVD/128, MROWS/128), 256, GM_SMEM>>>(
        hidden, w1, qkvh, QKVD, 1024);

    // 2. rope + feature projection on tensor cores (+ fused kp rowsums)
    ropeproj_kernel<<<(MROWS*24)/64, 128>>>(cosg, sing, proj);
    // 3. z scan
    zscan_kernel<<<Bv*NKVH, 256>>>();
    // 4. per-chunk KV (mma.sync)
    chunkkv_kernel<<<dim3(NCHUNK, Bv*NKVH), 128>>>();
    // 5. exclusive chunk prefix (4-way parallel over vector)
    kvprefix_kernel<<<dim3(Bv*NKVH, 4), 256>>>();
    // 6. causal combine (1-pass fp16) -> fp16 attn into g_ah
    stage_d_kernel<<<dim3(NCHUNK, NHEAD, Bv), 256, SD_BYTES>>>();

    // 7. convert W_o; output GEMM reads fp16 attn, writes fp32 out
    cvt_h_kernel<<<(1024*1024)/1024, 256>>>(W_o, w2, 1024*1024);
    gemm_mma_kernel<__half, float><<<dim3(1024/128, MROWS/128), 256, GM_SMEM>>>(
        ah, w2, out, 1024, 1024);
}